// round 7
// baseline (speedup 1.0000x reference)
#include <cuda_runtime.h>

#define NBINS 32
#define NROWS 34                  /* bin 0 = identity-low, 1..32 real, 33 = identity-high */
#define NDIM 64
#define NCELL 66                  /* cell 0 = below range, 1..64 interior, 65 = above */
#define RMIN (-5.0f)
#define THREADS 512
#define BLOCKS 296                /* 148 SMs x 2 CTAs: one persistent wave */
#define STRIDE (BLOCKS * THREADS) /* 151552, compile-time */
#define U 8                       /* pipeline batch */

/* smem layout (all [row][dim]: consecutive lanes = consecutive dims = no
   bank conflicts regardless of divergent row index):
   rec4 [NROWS][NDIM] float4 {xk, P2, P1, yk}   34816 B
   rec2 [NROWS][NDIM] float2 {C, D}             17408 B
   cell [NCELL][NDIM] float  (bnd|jlo in low 6) 16896 B
   kxf  [NBINS+1][NDIM] float                    8448 B  -> 77568 B, 2 CTAs/SM */
#define OFF_REC2 34816
#define OFF_CELL (34816 + 17408)
#define OFF_KXF  (34816 + 17408 + 16896)
#define SMEM_BYTES (OFF_KXF + 8448)

__device__ __forceinline__ int bin_of(float v, const float* __restrict__ celld)
{
    /* cell = floor((v+5)*6.4)+1 = floor(6.4v+33), clamped to [0,65] */
    int c = __float2int_rd(fmaf(v, 6.4f, 33.0f));
    c = min(max(c, 0), NCELL - 1);
    const int b = __float_as_int(celld[c * NDIM]);
    /* low 6 bits of the boundary float hold jlo; +-63 ulp boundary shift is
       harmless: the spline is continuous across knots */
    return (b & 63) + ((v >= __int_as_float(b)) ? 1 : 0);
}

__device__ __forceinline__ float eval1(float v, int j,
                                       const float4* __restrict__ rec4d,
                                       const float2* __restrict__ rec2d)
{
    const float4 ra = rec4d[j * NDIM];
    const float2 rb = rec2d[j * NDIM];
    const float u = v - ra.x;
    const float num = fmaf(fmaf(ra.y, u, ra.z), u, ra.w);
    const float den = fmaf(fmaf(rb.x, u, rb.y), u, 1.0f);
    return __fdividef(num, den);   /* identity rows: num=v, den=1 -> y=v */
}

__device__ __forceinline__ void eval_batch(
    const float* __restrict__ xv,
    const float* __restrict__ celld,
    const float4* __restrict__ rec4d,
    const float2* __restrict__ rec2d,
    float* __restrict__ out, int i)
{
    int jj[U];
    #pragma unroll
    for (int u = 0; u < U; ++u) jj[u] = bin_of(xv[u], celld);
    #pragma unroll
    for (int u = 0; u < U; ++u)
        out[i + u * STRIDE] = eval1(xv[u], jj[u], rec4d, rec2d);
}

__global__ __launch_bounds__(THREADS, 2) void rqspline_kernel(
    const float* __restrict__ x,
    const float* __restrict__ bw,
    const float* __restrict__ bh,
    const float* __restrict__ ks,
    float* __restrict__ out,
    int total)
{
    extern __shared__ __align__(16) char smem[];
    float4* rec4 = (float4*)smem;
    float2* rec2 = (float2*)(smem + OFF_REC2);
    float*  cell = (float*) (smem + OFF_CELL);
    float*  kxf  = (float*) (smem + OFF_KXF);

    const int t = threadIdx.x;
    const int tid = blockIdx.x * THREADS + t;

    /* ---- prefetch batch 0 BEFORE table build: LDGs fly during build ---- */
    float xc[U];
    const bool full0 = (tid + (U - 1) * STRIDE < total);
    if (full0) {
        #pragma unroll
        for (int u = 0; u < U; ++u) xc[u] = __ldg(x + tid + u * STRIDE);
    }

    /* ---- phase 1: per-dim records; rows 0 and 33 encode identity ---- */
    if (t < NDIM) {
        rec4[t] = make_float4(0.0f, 0.0f, 1.0f, 0.0f);            /* num = v */
        rec2[t] = make_float2(0.0f, 0.0f);                        /* den = 1 */
        rec4[(NROWS - 1) * NDIM + t] = make_float4(0.0f, 0.0f, 1.0f, 0.0f);
        rec2[(NROWS - 1) * NDIM + t] = make_float2(0.0f, 0.0f);

        float cx = RMIN, cy = RMIN;
        #pragma unroll
        for (int jb = 0; jb < NBINS; ++jb) {
            const float nx = cx + bw[t * NBINS + jb];  /* reference fp32 cumsum */
            const float ny = cy + bh[t * NBINS + jb];
            const float wf = nx - cx;
            const float hf = ny - cy;
            const float dk  = (jb == 0) ? 1.0f : ks[t * (NBINS - 1) + jb - 1];
            const float dk1 = (jb == NBINS - 1) ? 1.0f : ks[t * (NBINS - 1) + jb];

            const float s = hf / wf;
            const float c = dk + dk1 - 2.0f * s;
            const float A = (s - dk) / wf;
            const float C = -c / (hf * wf);
            const float D = c / hf;
            const float P2 = fmaf(cy, C, A);
            const float P1 = fmaf(cy, D, dk);

            rec4[(jb + 1) * NDIM + t] = make_float4(cx, P2, P1, cy);
            rec2[(jb + 1) * NDIM + t] = make_float2(C, D);
            kxf[jb * NDIM + t] = cx;
            cx = nx; cy = ny;
        }
        kxf[NBINS * NDIM + t] = cx;
    }
    __syncthreads();

    /* ---- phase 2: cell table (66 cells), jlo packed in low 6 bits ---- */
    for (int e = t; e < NCELL * NDIM; e += THREADS) {
        const int c = e >> 6, d = e & (NDIM - 1);
        float bnd; int jlo;
        if (c == 0) {                      /* v < -5: never >= bnd -> row 0 */
            bnd = RMIN; jlo = 0;
        } else if (c == NCELL - 1) {       /* v >= 5: row 32 or 33 via hi */
            bnd = kxf[NBINS * NDIM + d]; jlo = NBINS;
        } else {
            const float cs = RMIN + (float)(c - 1) * 0.15625f;
            int j0 = min((c - 1) >> 1, NBINS - 1);
            while (j0 > 0 && kxf[j0 * NDIM + d] > cs) --j0;
            while (j0 < NBINS - 1 && kxf[(j0 + 1) * NDIM + d] <= cs) ++j0;
            jlo = j0 + 1;
            bnd = kxf[(j0 + 1) * NDIM + d];
        }
        cell[c * NDIM + d] =
            __int_as_float((__float_as_int(bnd) & ~63) | jlo);
    }
    __syncthreads();

    /* ---- phase 3: software-pipelined streaming eval ---- */
    const int d = tid & (NDIM - 1);      /* loop-invariant: STRIDE % 64 == 0 */
    const float4* rec4d = rec4 + d;
    const float2* rec2d = rec2 + d;
    const float*  celld = cell + d;

    int i = tid;
    for (; i + (2 * U - 1) * STRIDE < total; i += U * STRIDE) {
        float xn[U];
        #pragma unroll
        for (int u = 0; u < U; ++u)          /* next batch LDGs in flight */
            xn[u] = __ldg(x + i + (U + u) * STRIDE);
        eval_batch(xc, celld, rec4d, rec2d, out, i);
        #pragma unroll
        for (int u = 0; u < U; ++u) xc[u] = xn[u];
    }
    if (full0 && i + (U - 1) * STRIDE < total) {
        eval_batch(xc, celld, rec4d, rec2d, out, i);
        i += U * STRIDE;
    }
    for (; i < total; i += STRIDE) {
        const float v = __ldg(x + i);
        out[i] = eval1(v, bin_of(v, celld), rec4d, rec2d);
    }
}

extern "C" void kernel_launch(void* const* d_in, const int* in_sizes, int n_in,
                              void* d_out, int out_size) {
    const float* x  = (const float*)d_in[0];
    const float* bw = (const float*)d_in[1];
    const float* bh = (const float*)d_in[2];
    const float* ks = (const float*)d_in[3];
    float* out = (float*)d_out;
    const int total = in_sizes[0];

    cudaFuncSetAttribute(rqspline_kernel,
                         cudaFuncAttributeMaxDynamicSharedMemorySize, SMEM_BYTES);
    rqspline_kernel<<<BLOCKS, THREADS, SMEM_BYTES>>>(x, bw, bh, ks, out, total);
}

// round 8
// speedup vs baseline: 1.0461x; 1.0461x over previous
#include <cuda_runtime.h>

#define NBINS 32
#define NROWS 34                  /* bin 0 = identity-low, 1..32 real, 33 = identity-high */
#define NDIM 64
#define NCELL 66                  /* cell 0 = below range, 1..64 interior, 65 = above */
#define RMIN (-5.0f)
#define THREADS 640               /* 2 CTAs/SM -> 1280 thr = 40 warps (51 regs) */
#define BLOCKS 296                /* 148 SMs x 2 CTAs: one persistent wave */
#define STRIDE (BLOCKS * THREADS) /* 189440, compile-time */
#define U 8                       /* pipeline batch */

/* smem layout (all [row][dim]: consecutive lanes = consecutive dims = no
   bank conflicts regardless of divergent row index):
   rec4 [NROWS][NDIM] float4 {xk, P2, P1, yk}   34816 B
   rec2 [NROWS][NDIM] float2 {C, D}             17408 B
   cell [NCELL][NDIM] float  (bnd|jlo in low 6) 16896 B
   kxf  [NBINS+1][NDIM] float                    8448 B  -> 77568 B, 2 CTAs/SM */
#define OFF_REC2 34816
#define OFF_CELL (34816 + 17408)
#define OFF_KXF  (34816 + 17408 + 16896)
#define SMEM_BYTES (OFF_KXF + 8448)

__device__ __forceinline__ int bin_of(float v, const float* __restrict__ celld)
{
    /* cell = floor((v+5)*6.4)+1 = floor(6.4v+33), clamped to [0,65] */
    int c = __float2int_rd(fmaf(v, 6.4f, 33.0f));
    c = min(max(c, 0), NCELL - 1);
    const int b = __float_as_int(celld[c * NDIM]);
    /* low 6 bits of the boundary float hold jlo; +-63 ulp boundary shift is
       harmless: the spline is continuous across knots */
    return (b & 63) + ((v >= __int_as_float(b)) ? 1 : 0);
}

__device__ __forceinline__ float eval1(float v, int j,
                                       const float4* __restrict__ rec4d,
                                       const float2* __restrict__ rec2d)
{
    const float4 ra = rec4d[j * NDIM];
    const float2 rb = rec2d[j * NDIM];
    const float u = v - ra.x;
    const float num = fmaf(fmaf(ra.y, u, ra.z), u, ra.w);
    const float den = fmaf(fmaf(rb.x, u, rb.y), u, 1.0f);
    return __fdividef(num, den);   /* identity rows: num=v, den=1 -> y=v */
}

__device__ __forceinline__ void eval_batch(
    const float* __restrict__ xv,
    const float* __restrict__ celld,
    const float4* __restrict__ rec4d,
    const float2* __restrict__ rec2d,
    float* __restrict__ out, int i)
{
    int jj[U];
    #pragma unroll
    for (int u = 0; u < U; ++u) jj[u] = bin_of(xv[u], celld);
    #pragma unroll
    for (int u = 0; u < U; ++u)
        out[i + u * STRIDE] = eval1(xv[u], jj[u], rec4d, rec2d);
}

__global__ __launch_bounds__(THREADS, 2) void rqspline_kernel(
    const float* __restrict__ x,
    const float* __restrict__ bw,
    const float* __restrict__ bh,
    const float* __restrict__ ks,
    float* __restrict__ out,
    int total)
{
    extern __shared__ __align__(16) char smem[];
    float4* rec4 = (float4*)smem;
    float2* rec2 = (float2*)(smem + OFF_REC2);
    float*  cell = (float*) (smem + OFF_CELL);
    float*  kxf  = (float*) (smem + OFF_KXF);

    const int t = threadIdx.x;
    const int tid = blockIdx.x * THREADS + t;

    /* ---- prefetch batch 0 BEFORE table build: LDGs fly during build ---- */
    float xc[U];
    const bool full0 = (tid + (U - 1) * STRIDE < total);
    if (full0) {
        #pragma unroll
        for (int u = 0; u < U; ++u) xc[u] = __ldg(x + tid + u * STRIDE);
    }

    /* ---- phase 1: per-dim records; rows 0 and 33 encode identity ---- */
    if (t < NDIM) {
        rec4[t] = make_float4(0.0f, 0.0f, 1.0f, 0.0f);            /* num = v */
        rec2[t] = make_float2(0.0f, 0.0f);                        /* den = 1 */
        rec4[(NROWS - 1) * NDIM + t] = make_float4(0.0f, 0.0f, 1.0f, 0.0f);
        rec2[(NROWS - 1) * NDIM + t] = make_float2(0.0f, 0.0f);

        float cx = RMIN, cy = RMIN;
        #pragma unroll
        for (int jb = 0; jb < NBINS; ++jb) {
            const float nx = cx + bw[t * NBINS + jb];  /* reference fp32 cumsum */
            const float ny = cy + bh[t * NBINS + jb];
            const float wf = nx - cx;
            const float hf = ny - cy;
            const float dk  = (jb == 0) ? 1.0f : ks[t * (NBINS - 1) + jb - 1];
            const float dk1 = (jb == NBINS - 1) ? 1.0f : ks[t * (NBINS - 1) + jb];

            const float s = hf / wf;
            const float c = dk + dk1 - 2.0f * s;
            const float A = (s - dk) / wf;
            const float C = -c / (hf * wf);
            const float D = c / hf;
            const float P2 = fmaf(cy, C, A);
            const float P1 = fmaf(cy, D, dk);

            rec4[(jb + 1) * NDIM + t] = make_float4(cx, P2, P1, cy);
            rec2[(jb + 1) * NDIM + t] = make_float2(C, D);
            kxf[jb * NDIM + t] = cx;
            cx = nx; cy = ny;
        }
        kxf[NBINS * NDIM + t] = cx;
    }
    __syncthreads();

    /* ---- phase 2: cell table (66 cells), jlo packed in low 6 bits ---- */
    for (int e = t; e < NCELL * NDIM; e += THREADS) {
        const int c = e >> 6, d = e & (NDIM - 1);
        float bnd; int jlo;
        if (c == 0) {                      /* v < -5: never >= bnd -> row 0 */
            bnd = RMIN; jlo = 0;
        } else if (c == NCELL - 1) {       /* v >= 5: row 32 or 33 via hi */
            bnd = kxf[NBINS * NDIM + d]; jlo = NBINS;
        } else {
            const float cs = RMIN + (float)(c - 1) * 0.15625f;
            int j0 = min((c - 1) >> 1, NBINS - 1);
            while (j0 > 0 && kxf[j0 * NDIM + d] > cs) --j0;
            while (j0 < NBINS - 1 && kxf[(j0 + 1) * NDIM + d] <= cs) ++j0;
            jlo = j0 + 1;
            bnd = kxf[(j0 + 1) * NDIM + d];
        }
        cell[c * NDIM + d] =
            __int_as_float((__float_as_int(bnd) & ~63) | jlo);
    }
    __syncthreads();

    /* ---- phase 3: software-pipelined streaming eval ---- */
    const int d = tid & (NDIM - 1);      /* loop-invariant: STRIDE % 64 == 0 */
    const float4* rec4d = rec4 + d;
    const float2* rec2d = rec2 + d;
    const float*  celld = cell + d;

    int i = tid;
    for (; i + (2 * U - 1) * STRIDE < total; i += U * STRIDE) {
        float xn[U];
        #pragma unroll
        for (int u = 0; u < U; ++u)          /* next batch LDGs in flight */
            xn[u] = __ldg(x + i + (U + u) * STRIDE);
        eval_batch(xc, celld, rec4d, rec2d, out, i);
        #pragma unroll
        for (int u = 0; u < U; ++u) xc[u] = xn[u];
    }
    if (full0 && i + (U - 1) * STRIDE < total) {
        eval_batch(xc, celld, rec4d, rec2d, out, i);
        i += U * STRIDE;
    }
    for (; i < total; i += STRIDE) {
        const float v = __ldg(x + i);
        out[i] = eval1(v, bin_of(v, celld), rec4d, rec2d);
    }
}

extern "C" void kernel_launch(void* const* d_in, const int* in_sizes, int n_in,
                              void* d_out, int out_size) {
    const float* x  = (const float*)d_in[0];
    const float* bw = (const float*)d_in[1];
    const float* bh = (const float*)d_in[2];
    const float* ks = (const float*)d_in[3];
    float* out = (float*)d_out;
    const int total = in_sizes[0];

    cudaFuncSetAttribute(rqspline_kernel,
                         cudaFuncAttributeMaxDynamicSharedMemorySize, SMEM_BYTES);
    rqspline_kernel<<<BLOCKS, THREADS, SMEM_BYTES>>>(x, bw, bh, ks, out, total);
}

// round 9
// speedup vs baseline: 1.0580x; 1.0113x over previous
#include <cuda_runtime.h>
#include <cuda_fp16.h>

#define NBINS 32
#define NROWS 34                  /* row 0 = identity-low, 1..32 real, 33 = identity-high */
#define NDIM 64
#define NCELL 66                  /* cell 0 = below range, 1..64 interior, 65 = above */
#define RMIN (-5.0f)
#define THREADS 640               /* 2 CTAs/SM -> 1280 thr = 40 warps */
#define BLOCKS 296                /* 148 SMs x 2 CTAs: one persistent wave */
#define STRIDE (BLOCKS * THREADS) /* 189440, compile-time */
#define U 8                       /* pipeline batch */

/* smem layout (all [row][dim]: consecutive lanes = consecutive dims = no
   bank conflicts regardless of divergent row index):
   rec  [NROWS][NDIM] float4 {xk, yk, (A,dk) f16x2, (C,D) f16x2}  34816 B
   cell [NCELL][NDIM] float  (bnd | jlo in low 6 bits)            16896 B
   kxf  [NBINS+1][NDIM] float                                      8448 B
   -> 60160 B, 2 CTAs/SM */
#define OFF_CELL 34816
#define OFF_KXF  (34816 + 16896)
#define SMEM_BYTES (OFF_KXF + 8448)

__device__ __forceinline__ int bin_of(float v, const float* __restrict__ celld)
{
    /* cell = floor((v+5)*6.4)+1 = floor(6.4v+33), clamped to [0,65] */
    int c = __float2int_rd(fmaf(v, 6.4f, 33.0f));
    c = min(max(c, 0), NCELL - 1);
    const int b = __float_as_int(celld[c * NDIM]);
    /* low 6 bits of boundary float hold jlo; the ~63-ulp boundary shift is
       harmless: the spline is continuous across knots */
    return (b & 63) + ((v >= __int_as_float(b)) ? 1 : 0);
}

__device__ __forceinline__ float eval1(float v, int j,
                                       const float4* __restrict__ recd)
{
    const float4 r = recd[j * NDIM];
    const float u = v - r.x;
    const float2 ab = __half22float2(*(const __half2*)&r.z);  /* A, dk */
    const float2 cd = __half22float2(*(const __half2*)&r.w);  /* C, D  */
    const float num = u * fmaf(ab.x, u, ab.y);
    const float den = fmaf(u, fmaf(cd.x, u, cd.y), 1.0f);
    return r.y + __fdividef(num, den);  /* identity rows: y = 0 + v/1 = v */
}

__device__ __forceinline__ void eval_batch(
    const float* __restrict__ xv,
    const float* __restrict__ celld,
    const float4* __restrict__ recd,
    float* __restrict__ out, int i)
{
    int jj[U];
    #pragma unroll
    for (int u = 0; u < U; ++u) jj[u] = bin_of(xv[u], celld);
    #pragma unroll
    for (int u = 0; u < U; ++u)
        out[i + u * STRIDE] = eval1(xv[u], jj[u], recd);
}

__global__ __launch_bounds__(THREADS, 2) void rqspline_kernel(
    const float* __restrict__ x,
    const float* __restrict__ bw,
    const float* __restrict__ bh,
    const float* __restrict__ ks,
    float* __restrict__ out,
    int total)
{
    extern __shared__ __align__(16) char smem[];
    float4* rec  = (float4*)smem;
    float*  cell = (float*) (smem + OFF_CELL);
    float*  kxf  = (float*) (smem + OFF_KXF);

    const int t = threadIdx.x;
    const int tid = blockIdx.x * THREADS + t;

    /* ---- prefetch batch 0 BEFORE table build: LDGs fly during build ---- */
    float xc[U];
    const bool full0 = (tid + (U - 1) * STRIDE < total);
    if (full0) {
        #pragma unroll
        for (int u = 0; u < U; ++u) xc[u] = __ldg(x + tid + u * STRIDE);
    }

    /* ---- phase 1: per-dim records; rows 0 and 33 encode identity ---- */
    if (t < NDIM) {
        const __half2 h01_id = __floats2half2_rn(0.0f, 1.0f);  /* A=0, dk=1 */
        const __half2 h23_id = __floats2half2_rn(0.0f, 0.0f);  /* C=0, D=0  */
        float4 rid;
        rid.x = 0.0f; rid.y = 0.0f;
        rid.z = __uint_as_float(*(const unsigned*)&h01_id);
        rid.w = __uint_as_float(*(const unsigned*)&h23_id);
        rec[t] = rid;
        rec[(NROWS - 1) * NDIM + t] = rid;

        float cx = RMIN, cy = RMIN;
        #pragma unroll
        for (int jb = 0; jb < NBINS; ++jb) {
            const float nx = cx + bw[t * NBINS + jb];  /* reference fp32 cumsum */
            const float ny = cy + bh[t * NBINS + jb];
            const float wf = nx - cx;
            const float hf = ny - cy;
            const float dk  = (jb == 0) ? 1.0f : ks[t * (NBINS - 1) + jb - 1];
            const float dk1 = (jb == NBINS - 1) ? 1.0f : ks[t * (NBINS - 1) + jb];

            const float s = hf / wf;
            const float c = dk + dk1 - 2.0f * s;
            const float A = (s - dk) / wf;
            const float C = -c / (hf * wf);
            const float D = c / hf;

            float4 r;
            r.x = cx; r.y = cy;
            const __half2 h01 = __floats2half2_rn(A, dk);
            const __half2 h23 = __floats2half2_rn(C, D);
            r.z = __uint_as_float(*(const unsigned*)&h01);
            r.w = __uint_as_float(*(const unsigned*)&h23);
            rec[(jb + 1) * NDIM + t] = r;
            kxf[jb * NDIM + t] = cx;
            cx = nx; cy = ny;
        }
        kxf[NBINS * NDIM + t] = cx;
    }
    __syncthreads();

    /* ---- phase 2: cell table (66 cells), jlo packed in low 6 bits ---- */
    for (int e = t; e < NCELL * NDIM; e += THREADS) {
        const int c = e >> 6, d = e & (NDIM - 1);
        float bnd; int jlo;
        if (c == 0) {                      /* v < -5: never >= bnd -> row 0 */
            bnd = RMIN; jlo = 0;
        } else if (c == NCELL - 1) {       /* v >= 5: row 32 or 33 via hi */
            bnd = kxf[NBINS * NDIM + d]; jlo = NBINS;
        } else {
            const float cs = RMIN + (float)(c - 1) * 0.15625f;
            int j0 = min((c - 1) >> 1, NBINS - 1);
            while (j0 > 0 && kxf[j0 * NDIM + d] > cs) --j0;
            while (j0 < NBINS - 1 && kxf[(j0 + 1) * NDIM + d] <= cs) ++j0;
            jlo = j0 + 1;
            bnd = kxf[(j0 + 1) * NDIM + d];
        }
        cell[c * NDIM + d] =
            __int_as_float((__float_as_int(bnd) & ~63) | jlo);
    }
    __syncthreads();

    /* ---- phase 3: software-pipelined streaming eval ---- */
    const int d = tid & (NDIM - 1);      /* loop-invariant: STRIDE % 64 == 0 */
    const float4* recd  = rec  + d;
    const float*  celld = cell + d;

    int i = tid;
    for (; i + (2 * U - 1) * STRIDE < total; i += U * STRIDE) {
        float xn[U];
        #pragma unroll
        for (int u = 0; u < U; ++u)          /* next batch LDGs in flight */
            xn[u] = __ldg(x + i + (U + u) * STRIDE);
        eval_batch(xc, celld, recd, out, i);
        #pragma unroll
        for (int u = 0; u < U; ++u) xc[u] = xn[u];
    }
    if (full0 && i + (U - 1) * STRIDE < total) {
        eval_batch(xc, celld, recd, out, i);
        i += U * STRIDE;
    }
    for (; i < total; i += STRIDE) {
        const float v = __ldg(x + i);
        out[i] = eval1(v, bin_of(v, celld), recd);
    }
}

extern "C" void kernel_launch(void* const* d_in, const int* in_sizes, int n_in,
                              void* d_out, int out_size) {
    const float* x  = (const float*)d_in[0];
    const float* bw = (const float*)d_in[1];
    const float* bh = (const float*)d_in[2];
    const float* ks = (const float*)d_in[3];
    float* out = (float*)d_out;
    const int total = in_sizes[0];

    cudaFuncSetAttribute(rqspline_kernel,
                         cudaFuncAttributeMaxDynamicSharedMemorySize, SMEM_BYTES);
    rqspline_kernel<<<BLOCKS, THREADS, SMEM_BYTES>>>(x, bw, bh, ks, out, total);
}

// round 10
// speedup vs baseline: 1.0607x; 1.0026x over previous
#include <cuda_runtime.h>
#include <cuda_fp16.h>

#define NBINS 32
#define NROWS 34                  /* row 0 = identity-low, 1..32 real, 33 = identity-high */
#define NDIM 64
#define NCELL 66                  /* cell 0 = below range, 1..64 interior, 65 = above */
#define RMIN (-5.0f)
#define THREADS 768               /* 2 CTAs/SM -> 1536 thr = 48 warps */
#define BLOCKS 296                /* 148 SMs x 2 CTAs: one persistent wave */
#define STRIDE (BLOCKS * THREADS) /* 227328, compile-time, ==0 mod 64 */
#define U 6                       /* pipeline batch (trimmed for 40-reg budget) */

/* smem layout (all [row][dim]: consecutive lanes = consecutive dims = no
   bank conflicts regardless of divergent row index):
   rec  [NROWS][NDIM] float4 {xk, yk, (A,dk) f16x2, (C,D) f16x2}  34816 B
   cell [NCELL][NDIM] float  (bnd | jlo in low 6 bits)            16896 B
   kxf  [NBINS+1][NDIM] float                                      8448 B
   -> 60160 B, 2 CTAs/SM */
#define OFF_CELL 34816
#define OFF_KXF  (34816 + 16896)
#define SMEM_BYTES (OFF_KXF + 8448)

__device__ __forceinline__ int bin_of(float v, const float* __restrict__ celld)
{
    /* cell = floor((v+5)*6.4)+1 = floor(6.4v+33), clamped to [0,65] */
    int c = __float2int_rd(fmaf(v, 6.4f, 33.0f));
    c = min(max(c, 0), NCELL - 1);
    const int b = __float_as_int(celld[c * NDIM]);
    /* low 6 bits of boundary float hold jlo; the ~63-ulp boundary shift is
       harmless: the spline is continuous across knots */
    return (b & 63) + ((v >= __int_as_float(b)) ? 1 : 0);
}

__device__ __forceinline__ float eval1(float v, int j,
                                       const float4* __restrict__ recd)
{
    const float4 r = recd[j * NDIM];
    const float u = v - r.x;
    const float2 ab = __half22float2(*(const __half2*)&r.z);  /* A, dk */
    const float2 cd = __half22float2(*(const __half2*)&r.w);  /* C, D  */
    const float num = u * fmaf(ab.x, u, ab.y);
    const float den = fmaf(u, fmaf(cd.x, u, cd.y), 1.0f);
    return r.y + __fdividef(num, den);  /* identity rows: y = 0 + v/1 = v */
}

__device__ __forceinline__ void eval_batch(
    const float* __restrict__ xv,
    const float* __restrict__ celld,
    const float4* __restrict__ recd,
    float* __restrict__ out, int i)
{
    int jj[U];
    #pragma unroll
    for (int u = 0; u < U; ++u) jj[u] = bin_of(xv[u], celld);
    #pragma unroll
    for (int u = 0; u < U; ++u)
        out[i + u * STRIDE] = eval1(xv[u], jj[u], recd);
}

__global__ __launch_bounds__(THREADS, 2) void rqspline_kernel(
    const float* __restrict__ x,
    const float* __restrict__ bw,
    const float* __restrict__ bh,
    const float* __restrict__ ks,
    float* __restrict__ out,
    int total)
{
    extern __shared__ __align__(16) char smem[];
    float4* rec  = (float4*)smem;
    float*  cell = (float*) (smem + OFF_CELL);
    float*  kxf  = (float*) (smem + OFF_KXF);

    const int t = threadIdx.x;
    const int tid = blockIdx.x * THREADS + t;

    /* ---- prefetch batch 0 BEFORE table build: LDGs fly during build ---- */
    float xc[U];
    const bool full0 = (tid + (U - 1) * STRIDE < total);
    if (full0) {
        #pragma unroll
        for (int u = 0; u < U; ++u) xc[u] = __ldg(x + tid + u * STRIDE);
    }

    /* ---- phase 1: per-dim records; rows 0 and 33 encode identity ---- */
    if (t < NDIM) {
        const __half2 h01_id = __floats2half2_rn(0.0f, 1.0f);  /* A=0, dk=1 */
        const __half2 h23_id = __floats2half2_rn(0.0f, 0.0f);  /* C=0, D=0  */
        float4 rid;
        rid.x = 0.0f; rid.y = 0.0f;
        rid.z = __uint_as_float(*(const unsigned*)&h01_id);
        rid.w = __uint_as_float(*(const unsigned*)&h23_id);
        rec[t] = rid;
        rec[(NROWS - 1) * NDIM + t] = rid;

        float cx = RMIN, cy = RMIN;
        #pragma unroll
        for (int jb = 0; jb < NBINS; ++jb) {
            const float nx = cx + bw[t * NBINS + jb];  /* reference fp32 cumsum */
            const float ny = cy + bh[t * NBINS + jb];
            const float wf = nx - cx;
            const float hf = ny - cy;
            const float dk  = (jb == 0) ? 1.0f : ks[t * (NBINS - 1) + jb - 1];
            const float dk1 = (jb == NBINS - 1) ? 1.0f : ks[t * (NBINS - 1) + jb];

            const float s = hf / wf;
            const float c = dk + dk1 - 2.0f * s;
            const float A = (s - dk) / wf;
            const float C = -c / (hf * wf);
            const float D = c / hf;

            float4 r;
            r.x = cx; r.y = cy;
            const __half2 h01 = __floats2half2_rn(A, dk);
            const __half2 h23 = __floats2half2_rn(C, D);
            r.z = __uint_as_float(*(const unsigned*)&h01);
            r.w = __uint_as_float(*(const unsigned*)&h23);
            rec[(jb + 1) * NDIM + t] = r;
            kxf[jb * NDIM + t] = cx;
            cx = nx; cy = ny;
        }
        kxf[NBINS * NDIM + t] = cx;
    }
    __syncthreads();

    /* ---- phase 2: cell table (66 cells), jlo packed in low 6 bits ---- */
    for (int e = t; e < NCELL * NDIM; e += THREADS) {
        const int c = e >> 6, d = e & (NDIM - 1);
        float bnd; int jlo;
        if (c == 0) {                      /* v < -5: never >= bnd -> row 0 */
            bnd = RMIN; jlo = 0;
        } else if (c == NCELL - 1) {       /* v >= 5: row 32 or 33 via hi */
            bnd = kxf[NBINS * NDIM + d]; jlo = NBINS;
        } else {
            const float cs = RMIN + (float)(c - 1) * 0.15625f;
            int j0 = min((c - 1) >> 1, NBINS - 1);
            while (j0 > 0 && kxf[j0 * NDIM + d] > cs) --j0;
            while (j0 < NBINS - 1 && kxf[(j0 + 1) * NDIM + d] <= cs) ++j0;
            jlo = j0 + 1;
            bnd = kxf[(j0 + 1) * NDIM + d];
        }
        cell[c * NDIM + d] =
            __int_as_float((__float_as_int(bnd) & ~63) | jlo);
    }
    __syncthreads();

    /* ---- phase 3: software-pipelined streaming eval ---- */
    const int d = tid & (NDIM - 1);      /* loop-invariant: STRIDE % 64 == 0 */
    const float4* recd  = rec  + d;
    const float*  celld = cell + d;

    int i = tid;
    for (; i + (2 * U - 1) * STRIDE < total; i += U * STRIDE) {
        float xn[U];
        #pragma unroll
        for (int u = 0; u < U; ++u)          /* next batch LDGs in flight */
            xn[u] = __ldg(x + i + (U + u) * STRIDE);
        eval_batch(xc, celld, recd, out, i);
        #pragma unroll
        for (int u = 0; u < U; ++u) xc[u] = xn[u];
    }
    if (full0 && i + (U - 1) * STRIDE < total) {
        eval_batch(xc, celld, recd, out, i);
        i += U * STRIDE;
    }
    for (; i < total; i += STRIDE) {
        const float v = __ldg(x + i);
        out[i] = eval1(v, bin_of(v, celld), recd);
    }
}

extern "C" void kernel_launch(void* const* d_in, const int* in_sizes, int n_in,
                              void* d_out, int out_size) {
    const float* x  = (const float*)d_in[0];
    const float* bw = (const float*)d_in[1];
    const float* bh = (const float*)d_in[2];
    const float* ks = (const float*)d_in[3];
    float* out = (float*)d_out;
    const int total = in_sizes[0];

    cudaFuncSetAttribute(rqspline_kernel,
                         cudaFuncAttributeMaxDynamicSharedMemorySize, SMEM_BYTES);
    rqspline_kernel<<<BLOCKS, THREADS, SMEM_BYTES>>>(x, bw, bh, ks, out, total);
}